// round 8
// baseline (speedup 1.0000x reference)
#include <cuda_runtime.h>
#include <math_constants.h>

// Problem constants
#define BB 4
#define NN 4096
#define F_IN 64
#define N_PROP 64
#define N_DIM 4
#define N_FILT 128
#define KN 39          // neighbors kept (top-40 minus self)
#define FULL 0xFFFFFFFFu
#define NBBUF 96
#define QPB 32         // queries per block (16 warps x 2)

// Scratch (allocation-free rule: __device__ globals)
__device__ float g_features[BB*NN*N_PROP];
__device__ float g_coords[BB*NN*N_DIM];
__device__ int   g_nbr_idx[BB*NN*KN];
__device__ float g_nbr_w[BB*NN*KN];

// ---------------------------------------------------------------------------
// K1: features = x@W_flr + b_flr ; coords = x@W_s + b_s
// Block = 32 rows, 256 threads; W in smem, 8 rows per thread.
// ---------------------------------------------------------------------------
__global__ void __launch_bounds__(256) k_feat(
    const float* __restrict__ x,
    const float* __restrict__ Wf, const float* __restrict__ bf,
    const float* __restrict__ Ws, const float* __restrict__ bs)
{
    __shared__ float Wfs[64*64];
    __shared__ float Wss[64*4];
    __shared__ float xs[32][64];

    int t = threadIdx.x;
    int row0 = blockIdx.x * 32;

    for (int k = t; k < 64*64/4; k += 256) ((float4*)Wfs)[k] = ((const float4*)Wf)[k];
    if (t < 64) ((float4*)Wss)[t] = ((const float4*)Ws)[t];
    for (int k = t; k < 32*64/4; k += 256)
        ((float4*)xs)[k] = ((const float4*)(x + row0 * F_IN))[k];
    __syncthreads();

    int j = t & 63, rg = t >> 6;            // rg owns rows rg*8 .. rg*8+7
    float b0 = bf[j];
    float a[8];
#pragma unroll
    for (int r = 0; r < 8; r++) a[r] = b0;
#pragma unroll
    for (int i = 0; i < 64; i++) {
        float wv = Wfs[i * 64 + j];
#pragma unroll
        for (int r = 0; r < 8; r++)
            a[r] = fmaf(xs[rg*8 + r][i], wv, a[r]);
    }
#pragma unroll
    for (int r = 0; r < 8; r++)
        g_features[(row0 + rg*8 + r) * N_PROP + j] = a[r];

    // coords: 128 threads cover 32 rows x 4 dims exactly
    if (t < 128) {
        int r = t >> 2, c = t & 3;          // r in [0,31], c in [0,3]
        float a2 = bs[c];
#pragma unroll
        for (int i = 0; i < 64; i++)
            a2 = fmaf(xs[r][i], Wss[i * 4 + c], a2);
        g_coords[(row0 + r) * N_DIM + c] = a2;
    }
}

// ---------------------------------------------------------------------------
// K2: 2 queries per warp, 16 warps/block (QPB=32), exact top-39.
// Distance: expanded form d = (pn[j]+qn) + sum(-2*q_i * p_i)  (1 FADD + 4 FMA)
// Pass A: 64-bin byte histogram, rotation-indexed column -> no atomics/chains.
// Reduce: dp4a column sums (self forced into bin 63, subtracted) -> t0.
// Pass C: uint key-threshold classification + ballot positioning;
//         boundary bin buffered, exact-rank fixup.
// smem: float4 sc[4096] 64K | float pn[4096] 16K | u8 hist[32][64][32] 64K
//       | uint2 bbuf[32][96] 24K  => 168K, 1 block/SM
// ---------------------------------------------------------------------------
// monotone 6-bit bin over the realistic distance range (exp 104..135)
__device__ __forceinline__ int bin6(uint key) {
    int b = (int)(key >> 22) - 208;
    return max(0, min(63, b));
}

__device__ __forceinline__ int find_t0(const uint* hw, int lane) {
    int b0 = 2 * lane, b1 = 2 * lane + 1;
    unsigned c0 = 0u, c1 = 0u;
#pragma unroll
    for (int k = 0; k < 8; k++) {
        c0 = __dp4a(hw[b0 * 8 + k], 0x01010101u, c0);
        c1 = __dp4a(hw[b1 * 8 + k], 0x01010101u, c1);
    }
    if (lane == 31) c1 -= 1u;     // self forced into bin 63
    int s = (int)c0 + (int)c1;
    int incl = s;
#pragma unroll
    for (int o = 1; o < 32; o <<= 1) {
        int v = __shfl_up_sync(FULL, incl, o);
        if (lane >= o) incl += v;
    }
    int excl = incl - s;
    uint ball = __ballot_sync(FULL, excl < KN && KN <= incl);
    int sel = __ffs(ball) - 1;
    int t0 = 0;
    if (lane == sel) t0 = (excl + (int)c0 >= KN) ? b0 : b1;
    return __shfl_sync(FULL, t0, sel);
}

__global__ void __launch_bounds__(512, 1) k_knn()
{
    extern __shared__ char smem_raw[];
    float4*        sc   = (float4*)smem_raw;                        // 65536
    float*         pn   = (float*)(smem_raw + 65536);               // 16384
    unsigned char* hist = (unsigned char*)(smem_raw + 81920);       // 65536
    uint2*         bbuf = (uint2*)(smem_raw + 147456);              // 24576

    int b = blockIdx.y;
    const float4* cp = (const float4*)(g_coords + b * NN * N_DIM);
    for (int i = threadIdx.x; i < NN; i += blockDim.x) {
        float4 v = cp[i];
        sc[i] = v;
        pn[i] = fmaf(v.x, v.x, fmaf(v.y, v.y, fmaf(v.z, v.z, v.w * v.w)));
    }
    __syncthreads();

    int w    = threadIdx.x >> 5;
    int lane = threadIdx.x & 31;
    int ql0  = 2 * w, ql1 = 2 * w + 1;       // block-local query ids
    int n0   = blockIdx.x * QPB + ql0;
    int n1   = n0 + 1;
    float4 q0 = sc[n0];
    float4 q1 = sc[n1];
    float qn0 = pn[n0], qn1 = pn[n1];
    float m0x = -2.f*q0.x, m0y = -2.f*q0.y, m0z = -2.f*q0.z, m0w = -2.f*q0.w;
    float m1x = -2.f*q1.x, m1y = -2.f*q1.y, m1z = -2.f*q1.z, m1w = -2.f*q1.w;
    unsigned char* h0 = hist + ql0 * 2048;
    unsigned char* h1 = hist + ql1 * 2048;
    uint lmask = (1u << lane) - 1u;

    // zero this warp's two histograms (4096 B total = 8 x uint4 per lane)
    {
        uint4 z = make_uint4(0, 0, 0, 0);
#pragma unroll
        for (int k = 0; k < 8; k++) ((uint4*)h0)[lane * 8 + k] = z;
    }
    __syncwarp();

    // ---- Pass A: byte histogram, rotated column kills RMW chains ----
#pragma unroll 4
    for (int t = 0; t < 128; t++) {
        int j = lane + 32 * t;
        float4 p = sc[j];
        float pnj = pn[j];
        float d0 = pnj + qn0;
        d0 = fmaf(m0x, p.x, d0); d0 = fmaf(m0y, p.y, d0);
        d0 = fmaf(m0z, p.z, d0); d0 = fmaf(m0w, p.w, d0);
        float d1 = pnj + qn1;
        d1 = fmaf(m1x, p.x, d1); d1 = fmaf(m1y, p.y, d1);
        d1 = fmaf(m1z, p.z, d1); d1 = fmaf(m1w, p.w, d1);
        uint k0 = (j == n0) ? 0xFFFFFFFFu : __float_as_uint(d0);
        uint k1 = (j == n1) ? 0xFFFFFFFFu : __float_as_uint(d1);
        int col = (lane + t) & 31;
        h0[(bin6(k0) << 5) + col]++;
        h1[(bin6(k1) << 5) + col]++;
    }
    __syncwarp();

    // ---- Reduce: boundary bins -> uint key thresholds ----
    int t0a = find_t0((const uint*)h0, lane);
    int t0b = find_t0((const uint*)h1, lane);
    uint lo0 = t0a ? ((uint)(t0a + 208) << 22) : 0u;
    uint hi0 = (t0a == 63) ? 0xFFFFFFFFu : ((uint)(t0a + 209) << 22);
    uint lo1 = t0b ? ((uint)(t0b + 208) << 22) : 0u;
    uint hi1 = (t0b == 63) ? 0xFFFFFFFFu : ((uint)(t0b + 209) << 22);

    // ---- Pass C: collect (key<lo accepted, lo<=key<hi buffered) ----
    int base0 = (b * NN + n0) * KN;
    int base1 = (b * NN + n1) * KN;
    int ca = 0, ba_ = 0;     // q0: accepted, boundary counts
    int cb = 0, bb_ = 0;     // q1
#pragma unroll 4
    for (int t = 0; t < 128; t++) {
        int j = lane + 32 * t;
        float4 p = sc[j];
        float pnj = pn[j];

        float d0 = pnj + qn0;
        d0 = fmaf(m0x, p.x, d0); d0 = fmaf(m0y, p.y, d0);
        d0 = fmaf(m0z, p.z, d0); d0 = fmaf(m0w, p.w, d0);
        uint k0 = (j == n0) ? 0xFFFFFFFFu : __float_as_uint(d0);
        bool ac0 = k0 < lo0;
        bool bd0 = !ac0 && k0 < hi0;
        uint A0 = __ballot_sync(FULL, ac0);
        uint B0 = __ballot_sync(FULL, bd0);
        if (ac0) {
            int pos = ca + __popc(A0 & lmask);
            g_nbr_idx[base0 + pos] = j;
            g_nbr_w[base0 + pos]   = __expf(-10.0f * d0);
        }
        if (bd0) {
            int bp = ba_ + __popc(B0 & lmask);
            if (bp < NBBUF) bbuf[ql0 * NBBUF + bp] = make_uint2(k0, (uint)j);
        }
        ca  += __popc(A0);
        ba_ += __popc(B0);

        float d1 = pnj + qn1;
        d1 = fmaf(m1x, p.x, d1); d1 = fmaf(m1y, p.y, d1);
        d1 = fmaf(m1z, p.z, d1); d1 = fmaf(m1w, p.w, d1);
        uint k1 = (j == n1) ? 0xFFFFFFFFu : __float_as_uint(d1);
        bool ac1 = k1 < lo1;
        bool bd1 = !ac1 && k1 < hi1;
        uint A1 = __ballot_sync(FULL, ac1);
        uint B1 = __ballot_sync(FULL, bd1);
        if (ac1) {
            int pos = cb + __popc(A1 & lmask);
            g_nbr_idx[base1 + pos] = j;
            g_nbr_w[base1 + pos]   = __expf(-10.0f * d1);
        }
        if (bd1) {
            int bp = bb_ + __popc(B1 & lmask);
            if (bp < NBBUF) bbuf[ql1 * NBBUF + bp] = make_uint2(k1, (uint)j);
        }
        cb  += __popc(A1);
        bb_ += __popc(B1);
    }
    __syncwarp();

    // ---- Boundary: exact rank among boundary candidates, per query ----
#pragma unroll
    for (int qq = 0; qq < 2; qq++) {
        int ql   = (qq == 0) ? ql0 : ql1;
        int need = KN - ((qq == 0) ? ca : cb);
        int M    = min((qq == 0) ? ba_ : bb_, NBBUF);
        int cpos = (qq == 0) ? ca : cb;
        int bse  = (qq == 0) ? base0 : base1;
        for (int r0 = 0; r0 < M; r0 += 32) {
            int sidx = r0 + lane;
            bool act = sidx < M;
            uint2 e = act ? bbuf[ql * NBBUF + sidx] : make_uint2(0u, 0u);
            int rank = 0;
            if (act) {
                for (int i = 0; i < M; i++) {
                    uint2 o = bbuf[ql * NBBUF + i];   // broadcast read
                    rank += (o.x < e.x) || (o.x == e.x && o.y < e.y);
                }
            }
            bool selp = act && rank < need;
            uint bs_ = __ballot_sync(FULL, selp);
            if (selp) {
                int pos = cpos + __popc(bs_ & lmask);
                g_nbr_idx[bse + pos] = (int)e.y;
                g_nbr_w[bse + pos]   = __expf(-10.0f * __uint_as_float(e.x));
            }
            cpos += __popc(bs_);
        }
    }
}

// ---------------------------------------------------------------------------
// K3: weighted gather -> max/mean -> concat -> @W_out + b_out.
// Warp handles 4 queries: each W_out float4 load feeds 16 FMAs.
// ---------------------------------------------------------------------------
__global__ void __launch_bounds__(256) k_agg(
    const float* __restrict__ x,
    const float* __restrict__ Wo, const float* __restrict__ bo,
    float* __restrict__ out)
{
    __shared__ float upd[32][192];
    int warp = threadIdx.x >> 5, lane = threadIdx.x & 31;
    int q0 = blockIdx.x * 32 + warp * 4;
    const float inv = 1.0f / 39.0f;

#pragma unroll
    for (int qq = 0; qq < 4; qq++) {
        int r = q0 + qq;
        const float* fb = g_features + (r >> 12) * NN * N_PROP;
        int bk = r * KN;
        float mx0 = -CUDART_INF_F, mx1 = -CUDART_INF_F, s0 = 0.f, s1 = 0.f;
#pragma unroll 8
        for (int k = 0; k < KN; k++) {
            int   jj = __ldg(&g_nbr_idx[bk + k]);
            float wt = __ldg(&g_nbr_w[bk + k]);
            float2 f = ((const float2*)(fb + jj * N_PROP))[lane];
            float v0 = wt * f.x, v1 = wt * f.y;
            mx0 = fmaxf(mx0, v0); mx1 = fmaxf(mx1, v1);
            s0 += v0; s1 += v1;
        }
        float2 xv = ((const float2*)(x + r * F_IN))[lane];
        int ql = warp * 4 + qq;
        upd[ql][2*lane]         = xv.x;
        upd[ql][2*lane + 1]     = xv.y;
        upd[ql][64 + 2*lane]    = mx0;
        upd[ql][64 + 2*lane+1]  = mx1;
        upd[ql][128 + 2*lane]   = s0 * inv;
        upd[ql][128 + 2*lane+1] = s1 * inv;
    }
    __syncwarp();

    float4 bv = ((const float4*)bo)[lane];
    float4 a0 = bv, a1 = bv, a2 = bv, a3 = bv;
    int ql0 = warp * 4;
#pragma unroll 4
    for (int c = 0; c < 192; c++) {
        float4 wv = ((const float4*)(Wo + c * N_FILT))[lane];
        float u0 = upd[ql0 + 0][c];
        float u1 = upd[ql0 + 1][c];
        float u2 = upd[ql0 + 2][c];
        float u3 = upd[ql0 + 3][c];
        a0.x = fmaf(u0, wv.x, a0.x); a0.y = fmaf(u0, wv.y, a0.y);
        a0.z = fmaf(u0, wv.z, a0.z); a0.w = fmaf(u0, wv.w, a0.w);
        a1.x = fmaf(u1, wv.x, a1.x); a1.y = fmaf(u1, wv.y, a1.y);
        a1.z = fmaf(u1, wv.z, a1.z); a1.w = fmaf(u1, wv.w, a1.w);
        a2.x = fmaf(u2, wv.x, a2.x); a2.y = fmaf(u2, wv.y, a2.y);
        a2.z = fmaf(u2, wv.z, a2.z); a2.w = fmaf(u2, wv.w, a2.w);
        a3.x = fmaf(u3, wv.x, a3.x); a3.y = fmaf(u3, wv.y, a3.y);
        a3.z = fmaf(u3, wv.z, a3.z); a3.w = fmaf(u3, wv.w, a3.w);
    }
    ((float4*)(out + (q0 + 0) * N_FILT))[lane] = a0;
    ((float4*)(out + (q0 + 1) * N_FILT))[lane] = a1;
    ((float4*)(out + (q0 + 2) * N_FILT))[lane] = a2;
    ((float4*)(out + (q0 + 3) * N_FILT))[lane] = a3;
}

// ---------------------------------------------------------------------------
extern "C" void kernel_launch(void* const* d_in, const int* in_sizes, int n_in,
                              void* d_out, int out_size)
{
    const float* x  = (const float*)d_in[0];
    const float* Wf = (const float*)d_in[1];
    const float* bf = (const float*)d_in[2];
    const float* Ws = (const float*)d_in[3];
    const float* bs = (const float*)d_in[4];
    const float* Wo = (const float*)d_in[5];
    const float* bo = (const float*)d_in[6];
    float* out = (float*)d_out;

    const int knn_smem = 65536 + 16384 + 65536 + QPB * NBBUF * 8;   // 172032
    cudaFuncSetAttribute(k_knn, cudaFuncAttributeMaxDynamicSharedMemorySize, knn_smem);

    k_feat<<<BB * NN / 32, 256>>>(x, Wf, bf, Ws, bs);

    dim3 g2(NN / QPB, BB);
    k_knn<<<g2, 512, knn_smem>>>();

    k_agg<<<BB * NN / 32, 256>>>(x, Wo, bo, out);
}

// round 9
// speedup vs baseline: 1.0351x; 1.0351x over previous
#include <cuda_runtime.h>
#include <math_constants.h>

// Problem constants
#define BB 4
#define NN 4096
#define F_IN 64
#define N_PROP 64
#define N_DIM 4
#define N_FILT 128
#define KN 39          // neighbors kept (top-40 minus self)
#define FULL 0xFFFFFFFFu
#define QPB 16         // queries per block (8 warps x 2)
#define NBUF 192       // per-query buffer slots: live [0..128), staging [64..192)

// Scratch (allocation-free rule: __device__ globals)
__device__ float g_features[BB*NN*N_PROP];
__device__ float g_coords[BB*NN*N_DIM];
__device__ int   g_nbr_idx[BB*NN*KN];
__device__ float g_nbr_w[BB*NN*KN];

// ---------------------------------------------------------------------------
// K1: features = x@W_flr + b_flr ; coords = x@W_s + b_s  (unchanged, passing)
// ---------------------------------------------------------------------------
__global__ void __launch_bounds__(256) k_feat(
    const float* __restrict__ x,
    const float* __restrict__ Wf, const float* __restrict__ bf,
    const float* __restrict__ Ws, const float* __restrict__ bs)
{
    __shared__ float Wfs[64*64];
    __shared__ float Wss[64*4];
    __shared__ float xs[32][64];

    int t = threadIdx.x;
    int row0 = blockIdx.x * 32;

    for (int k = t; k < 64*64/4; k += 256) ((float4*)Wfs)[k] = ((const float4*)Wf)[k];
    if (t < 64) ((float4*)Wss)[t] = ((const float4*)Ws)[t];
    for (int k = t; k < 32*64/4; k += 256)
        ((float4*)xs)[k] = ((const float4*)(x + row0 * F_IN))[k];
    __syncthreads();

    int j = t & 63, rg = t >> 6;
    float b0 = bf[j];
    float a[8];
#pragma unroll
    for (int r = 0; r < 8; r++) a[r] = b0;
#pragma unroll
    for (int i = 0; i < 64; i++) {
        float wv = Wfs[i * 64 + j];
#pragma unroll
        for (int r = 0; r < 8; r++)
            a[r] = fmaf(xs[rg*8 + r][i], wv, a[r]);
    }
#pragma unroll
    for (int r = 0; r < 8; r++)
        g_features[(row0 + rg*8 + r) * N_PROP + j] = a[r];

    if (t < 128) {
        int r = t >> 2, c = t & 3;
        float a2 = bs[c];
#pragma unroll
        for (int i = 0; i < 64; i++)
            a2 = fmaf(xs[r][i], Wss[i * 4 + c], a2);
        g_coords[(row0 + r) * N_DIM + c] = a2;
    }
}

// ---------------------------------------------------------------------------
// K2: single-pass online-threshold exact top-39, 2 queries per warp.
// Accept key<th into a 128-slot buffer; exact compact-to-39 when >96; th
// tightens to the boundary bin's upper edge. Exact by construction.
// smem: float4 sc[4096] 64K | float pn[4096] 16K
//       | uint2 bufs[16][192] 24K | uint hists[16][64] 4K  => 108K, 2 blk/SM
// ---------------------------------------------------------------------------
__device__ __forceinline__ int bin6(uint key) {
    int b = (int)(key >> 22) - 208;
    return max(0, min(63, b));
}

// Exact: keep the 39 lex-smallest (key,idx) of buf[0..M) into buf[0..39)
// (unordered), set *th to boundary-bin upper edge. Warp-collective, M<=128.
__device__ __forceinline__ int compact39(uint2* buf, uint* hist, int M,
                                         int lane, uint lmask, uint* th)
{
    hist[2*lane] = 0u; hist[2*lane + 1] = 0u;
    __syncwarp();
    uint2 e[4];
#pragma unroll
    for (int i = 0; i < 4; i++) {
        int s = lane + 32*i;
        if (s < M) { e[i] = buf[s]; atomicAdd(&hist[bin6(e[i].x)], 1u); }
    }
    __syncwarp();
    uint h0 = hist[2*lane], h1 = hist[2*lane + 1];
    int sum = (int)(h0 + h1), incl = sum;
#pragma unroll
    for (int o = 1; o < 32; o <<= 1) {
        int v = __shfl_up_sync(FULL, incl, o);
        if (lane >= o) incl += v;
    }
    int excl = incl - sum;
    uint ball = __ballot_sync(FULL, excl < KN && KN <= incl);
    int sel = __ffs(ball) - 1;
    int t0 = 0, nb = 0;
    if (lane == sel) {
        if (excl + (int)h0 >= KN) { t0 = 2*lane;     nb = excl; }
        else                      { t0 = 2*lane + 1; nb = excl + (int)h0; }
    }
    t0 = __shfl_sync(FULL, t0, sel);
    nb = __shfl_sync(FULL, nb, sel);
    int need = KN - nb;
    __syncwarp();                       // all reads into e[] done before rewrite

    // partition: bin<t0 -> buf[0..nb), bin==t0 -> staging buf[64..64+B)
    int ca = 0, bb = 0;
#pragma unroll
    for (int i = 0; i < 4; i++) {
        int s = lane + 32*i;
        bool act = s < M;
        int bn = act ? bin6(e[i].x) : 64;
        bool bel = bn < t0;
        bool bnd = bn == t0;
        uint A = __ballot_sync(FULL, bel);
        uint B = __ballot_sync(FULL, bnd);
        if (bel) buf[ca + __popc(A & lmask)] = e[i];
        if (bnd) buf[64 + bb + __popc(B & lmask)] = e[i];
        ca += __popc(A);
        bb += __popc(B);
    }
    __syncwarp();

    // exact rank within boundary set, fill remaining need slots
    int cpos = ca;                      // == nb
    for (int r0 = 0; r0 < bb; r0 += 32) {
        int s = r0 + lane;
        bool act = s < bb;
        uint2 ee = act ? buf[64 + s] : make_uint2(0u, 0u);
        int rank = 0;
        if (act) {
            for (int i = 0; i < bb; i++) {
                uint2 o = buf[64 + i];          // broadcast read
                rank += (o.x < ee.x) || (o.x == ee.x && o.y < ee.y);
            }
        }
        bool kp = act && rank < need;
        uint Kb = __ballot_sync(FULL, kp);
        if (kp) buf[cpos + __popc(Kb & lmask)] = ee;   // cpos..38 < 64: no clash
        cpos += __popc(Kb);
    }
    __syncwarp();
    *th = (t0 >= 63) ? 0xFFFFFFFFu : ((uint)(t0 + 209) << 22);
    return KN;
}

__global__ void __launch_bounds__(256, 2) k_knn()
{
    extern __shared__ char smem_raw[];
    float4* sc    = (float4*)smem_raw;                        // 65536
    float*  pn    = (float*)(smem_raw + 65536);               // 16384
    uint2*  bufs  = (uint2*)(smem_raw + 81920);               // 24576
    uint*   hists = (uint*)(smem_raw + 81920 + 24576);        // 4096

    int b = blockIdx.y;
    const float4* cp = (const float4*)(g_coords + b * NN * N_DIM);
    for (int i = threadIdx.x; i < NN; i += blockDim.x) {
        float4 v = cp[i];
        sc[i] = v;
        pn[i] = fmaf(v.x, v.x, fmaf(v.y, v.y, fmaf(v.z, v.z, v.w * v.w)));
    }
    __syncthreads();

    int w    = threadIdx.x >> 5;
    int lane = threadIdx.x & 31;
    int ql0  = 2 * w, ql1 = 2 * w + 1;
    int n0   = blockIdx.x * QPB + ql0;
    int n1   = n0 + 1;
    float4 q0 = sc[n0];
    float4 q1 = sc[n1];
    float qn0 = pn[n0], qn1 = pn[n1];
    float m0x = -2.f*q0.x, m0y = -2.f*q0.y, m0z = -2.f*q0.z, m0w = -2.f*q0.w;
    float m1x = -2.f*q1.x, m1y = -2.f*q1.y, m1z = -2.f*q1.z, m1w = -2.f*q1.w;
    uint2* buf0 = bufs + ql0 * NBUF;
    uint2* buf1 = bufs + ql1 * NBUF;
    uint*  h0   = hists + ql0 * 64;
    uint*  h1   = hists + ql1 * 64;
    uint lmask = (1u << lane) - 1u;

    uint th0 = FULL, th1 = FULL;
    int  c0 = 0, c1 = 0;

    for (int t = 0; t < 128; t++) {
        int j = lane + 32 * t;
        float4 p = sc[j];
        float pnj = pn[j];

        float d0 = pnj + qn0;
        d0 = fmaf(m0x, p.x, d0); d0 = fmaf(m0y, p.y, d0);
        d0 = fmaf(m0z, p.z, d0); d0 = fmaf(m0w, p.w, d0);
        d0 = fmaxf(d0, 0.f);
        uint k0 = (j == n0) ? FULL : __float_as_uint(d0);

        float d1 = pnj + qn1;
        d1 = fmaf(m1x, p.x, d1); d1 = fmaf(m1y, p.y, d1);
        d1 = fmaf(m1z, p.z, d1); d1 = fmaf(m1w, p.w, d1);
        d1 = fmaxf(d1, 0.f);
        uint k1 = (j == n1) ? FULL : __float_as_uint(d1);

        bool a0 = k0 < th0;
        uint A0 = __ballot_sync(FULL, a0);
        if (A0) {
            if (a0) buf0[c0 + __popc(A0 & lmask)] = make_uint2(k0, (uint)j);
            c0 += __popc(A0);
        }
        bool a1 = k1 < th1;
        uint A1 = __ballot_sync(FULL, a1);
        if (A1) {
            if (a1) buf1[c1 + __popc(A1 & lmask)] = make_uint2(k1, (uint)j);
            c1 += __popc(A1);
        }
        if ((c0 | c1) > 96) {           // cheap combined trigger, exact inner
            if (c0 > 96) c0 = compact39(buf0, h0, c0, lane, lmask, &th0);
            if (c1 > 96) c1 = compact39(buf1, h1, c1, lane, lmask, &th1);
        }
    }
    if (c0 > KN) c0 = compact39(buf0, h0, c0, lane, lmask, &th0);
    if (c1 > KN) c1 = compact39(buf1, h1, c1, lane, lmask, &th1);

    int base0 = (b * NN + n0) * KN;
    int base1 = (b * NN + n1) * KN;
    for (int s = lane; s < KN; s += 32) {
        uint2 e0 = buf0[s];
        g_nbr_idx[base0 + s] = (int)e0.y;
        g_nbr_w[base0 + s]   = __expf(-10.0f * __uint_as_float(e0.x));
        uint2 e1 = buf1[s];
        g_nbr_idx[base1 + s] = (int)e1.y;
        g_nbr_w[base1 + s]   = __expf(-10.0f * __uint_as_float(e1.x));
    }
}

// ---------------------------------------------------------------------------
// K3: weighted gather -> max/mean -> concat -> @W_out + b_out  (unchanged)
// ---------------------------------------------------------------------------
__global__ void __launch_bounds__(256) k_agg(
    const float* __restrict__ x,
    const float* __restrict__ Wo, const float* __restrict__ bo,
    float* __restrict__ out)
{
    __shared__ float upd[32][192];
    int warp = threadIdx.x >> 5, lane = threadIdx.x & 31;
    int q0 = blockIdx.x * 32 + warp * 4;
    const float inv = 1.0f / 39.0f;

#pragma unroll
    for (int qq = 0; qq < 4; qq++) {
        int r = q0 + qq;
        const float* fb = g_features + (r >> 12) * NN * N_PROP;
        int bk = r * KN;
        float mx0 = -CUDART_INF_F, mx1 = -CUDART_INF_F, s0 = 0.f, s1 = 0.f;
#pragma unroll 8
        for (int k = 0; k < KN; k++) {
            int   jj = __ldg(&g_nbr_idx[bk + k]);
            float wt = __ldg(&g_nbr_w[bk + k]);
            float2 f = ((const float2*)(fb + jj * N_PROP))[lane];
            float v0 = wt * f.x, v1 = wt * f.y;
            mx0 = fmaxf(mx0, v0); mx1 = fmaxf(mx1, v1);
            s0 += v0; s1 += v1;
        }
        float2 xv = ((const float2*)(x + r * F_IN))[lane];
        int ql = warp * 4 + qq;
        upd[ql][2*lane]         = xv.x;
        upd[ql][2*lane + 1]     = xv.y;
        upd[ql][64 + 2*lane]    = mx0;
        upd[ql][64 + 2*lane+1]  = mx1;
        upd[ql][128 + 2*lane]   = s0 * inv;
        upd[ql][128 + 2*lane+1] = s1 * inv;
    }
    __syncwarp();

    float4 bv = ((const float4*)bo)[lane];
    float4 a0 = bv, a1 = bv, a2 = bv, a3 = bv;
    int ql0 = warp * 4;
#pragma unroll 4
    for (int c = 0; c < 192; c++) {
        float4 wv = ((const float4*)(Wo + c * N_FILT))[lane];
        float u0 = upd[ql0 + 0][c];
        float u1 = upd[ql0 + 1][c];
        float u2 = upd[ql0 + 2][c];
        float u3 = upd[ql0 + 3][c];
        a0.x = fmaf(u0, wv.x, a0.x); a0.y = fmaf(u0, wv.y, a0.y);
        a0.z = fmaf(u0, wv.z, a0.z); a0.w = fmaf(u0, wv.w, a0.w);
        a1.x = fmaf(u1, wv.x, a1.x); a1.y = fmaf(u1, wv.y, a1.y);
        a1.z = fmaf(u1, wv.z, a1.z); a1.w = fmaf(u1, wv.w, a1.w);
        a2.x = fmaf(u2, wv.x, a2.x); a2.y = fmaf(u2, wv.y, a2.y);
        a2.z = fmaf(u2, wv.z, a2.z); a2.w = fmaf(u2, wv.w, a2.w);
        a3.x = fmaf(u3, wv.x, a3.x); a3.y = fmaf(u3, wv.y, a3.y);
        a3.z = fmaf(u3, wv.z, a3.z); a3.w = fmaf(u3, wv.w, a3.w);
    }
    ((float4*)(out + (q0 + 0) * N_FILT))[lane] = a0;
    ((float4*)(out + (q0 + 1) * N_FILT))[lane] = a1;
    ((float4*)(out + (q0 + 2) * N_FILT))[lane] = a2;
    ((float4*)(out + (q0 + 3) * N_FILT))[lane] = a3;
}

// ---------------------------------------------------------------------------
extern "C" void kernel_launch(void* const* d_in, const int* in_sizes, int n_in,
                              void* d_out, int out_size)
{
    const float* x  = (const float*)d_in[0];
    const float* Wf = (const float*)d_in[1];
    const float* bf = (const float*)d_in[2];
    const float* Ws = (const float*)d_in[3];
    const float* bs = (const float*)d_in[4];
    const float* Wo = (const float*)d_in[5];
    const float* bo = (const float*)d_in[6];
    float* out = (float*)d_out;

    const int knn_smem = 65536 + 16384 + QPB * NBUF * 8 + QPB * 64 * 4; // 110592
    cudaFuncSetAttribute(k_knn, cudaFuncAttributeMaxDynamicSharedMemorySize, knn_smem);

    k_feat<<<BB * NN / 32, 256>>>(x, Wf, bf, Ws, bs);

    dim3 g2(NN / QPB, BB);
    k_knn<<<g2, 256, knn_smem>>>();

    k_agg<<<BB * NN / 32, 256>>>(x, Wo, bo, out);
}

// round 10
// speedup vs baseline: 1.1130x; 1.0753x over previous
#include <cuda_runtime.h>
#include <math_constants.h>

// Problem constants
#define BB 4
#define NN 4096
#define F_IN 64
#define N_PROP 64
#define N_DIM 4
#define N_FILT 128
#define KN 39          // neighbors kept (top-40 minus self)
#define FULL 0xFFFFFFFFu
#define QPB 16         // queries per block (8 warps x 2)
#define NBUF 192       // per-query buffer slots: live [0..128), staging [64..192)

// Scratch (allocation-free rule: __device__ globals)
__device__ float g_features[BB*NN*N_PROP];
__device__ float g_coords[BB*NN*N_DIM];
__device__ int   g_nbr_idx[BB*NN*KN];
__device__ float g_nbr_w[BB*NN*KN];

// ---------------------------------------------------------------------------
// K1: features = x@W_flr + b_flr ; coords = x@W_s + b_s  (unchanged, passing)
// ---------------------------------------------------------------------------
__global__ void __launch_bounds__(256) k_feat(
    const float* __restrict__ x,
    const float* __restrict__ Wf, const float* __restrict__ bf,
    const float* __restrict__ Ws, const float* __restrict__ bs)
{
    __shared__ float Wfs[64*64];
    __shared__ float Wss[64*4];
    __shared__ float xs[32][64];

    int t = threadIdx.x;
    int row0 = blockIdx.x * 32;

    for (int k = t; k < 64*64/4; k += 256) ((float4*)Wfs)[k] = ((const float4*)Wf)[k];
    if (t < 64) ((float4*)Wss)[t] = ((const float4*)Ws)[t];
    for (int k = t; k < 32*64/4; k += 256)
        ((float4*)xs)[k] = ((const float4*)(x + row0 * F_IN))[k];
    __syncthreads();

    int j = t & 63, rg = t >> 6;
    float b0 = bf[j];
    float a[8];
#pragma unroll
    for (int r = 0; r < 8; r++) a[r] = b0;
#pragma unroll
    for (int i = 0; i < 64; i++) {
        float wv = Wfs[i * 64 + j];
#pragma unroll
        for (int r = 0; r < 8; r++)
            a[r] = fmaf(xs[rg*8 + r][i], wv, a[r]);
    }
#pragma unroll
    for (int r = 0; r < 8; r++)
        g_features[(row0 + rg*8 + r) * N_PROP + j] = a[r];

    if (t < 128) {
        int r = t >> 2, c = t & 3;
        float a2 = bs[c];
#pragma unroll
        for (int i = 0; i < 64; i++)
            a2 = fmaf(xs[r][i], Wss[i * 4 + c], a2);
        g_coords[(row0 + r) * N_DIM + c] = a2;
    }
}

// ---------------------------------------------------------------------------
// K2: single-pass online-threshold exact top-39, 2 queries per warp.
// BRANCH-FREE accept path: select-address + unconditional STS (no BSSY/BSYNC
// on the ballot result), so iterations pipeline. Exact compact-to-39 when a
// buffer exceeds 96; threshold tightens to the boundary bin's upper edge.
// smem: float4 sc[4096] 64K | float pn[4096] 16K | uint2 bufs[16][192] 24K
//       | uint hists[16][64] 4K | uint2 dump[8][32] 2K  => 110K, 2 blk/SM
// ---------------------------------------------------------------------------
__device__ __forceinline__ int bin6(uint key) {
    int b = (int)(key >> 22) - 208;
    return max(0, min(63, b));
}

// Exact: keep the 39 lex-smallest (key,idx) of buf[0..M) into buf[0..39)
// (unordered), set *th to boundary-bin upper edge. Warp-collective, M<=128.
__device__ __forceinline__ int compact39(uint2* buf, uint* hist, int M,
                                         int lane, uint lmask, uint* th)
{
    hist[2*lane] = 0u; hist[2*lane + 1] = 0u;
    __syncwarp();
    uint2 e[4];
#pragma unroll
    for (int i = 0; i < 4; i++) {
        int s = lane + 32*i;
        if (s < M) { e[i] = buf[s]; atomicAdd(&hist[bin6(e[i].x)], 1u); }
    }
    __syncwarp();
    uint h0 = hist[2*lane], h1 = hist[2*lane + 1];
    int sum = (int)(h0 + h1), incl = sum;
#pragma unroll
    for (int o = 1; o < 32; o <<= 1) {
        int v = __shfl_up_sync(FULL, incl, o);
        if (lane >= o) incl += v;
    }
    int excl = incl - sum;
    uint ball = __ballot_sync(FULL, excl < KN && KN <= incl);
    int sel = __ffs(ball) - 1;
    int t0 = 0, nb = 0;
    if (lane == sel) {
        if (excl + (int)h0 >= KN) { t0 = 2*lane;     nb = excl; }
        else                      { t0 = 2*lane + 1; nb = excl + (int)h0; }
    }
    t0 = __shfl_sync(FULL, t0, sel);
    nb = __shfl_sync(FULL, nb, sel);
    int need = KN - nb;
    __syncwarp();

    // partition: bin<t0 -> buf[0..nb), bin==t0 -> staging buf[64..64+B)
    int ca = 0, bb = 0;
#pragma unroll
    for (int i = 0; i < 4; i++) {
        int s = lane + 32*i;
        bool act = s < M;
        int bn = act ? bin6(e[i].x) : 64;
        bool bel = bn < t0;
        bool bnd = bn == t0;
        uint A = __ballot_sync(FULL, bel);
        uint B = __ballot_sync(FULL, bnd);
        if (bel) buf[ca + __popc(A & lmask)] = e[i];
        if (bnd) buf[64 + bb + __popc(B & lmask)] = e[i];
        ca += __popc(A);
        bb += __popc(B);
    }
    __syncwarp();

    // exact rank within boundary set, fill remaining need slots
    int cpos = ca;                      // == nb
    for (int r0 = 0; r0 < bb; r0 += 32) {
        int s = r0 + lane;
        bool act = s < bb;
        uint2 ee = act ? buf[64 + s] : make_uint2(0u, 0u);
        int rank = 0;
        if (act) {
            for (int i = 0; i < bb; i++) {
                uint2 o = buf[64 + i];          // broadcast read
                rank += (o.x < ee.x) || (o.x == ee.x && o.y < ee.y);
            }
        }
        bool kp = act && rank < need;
        uint Kb = __ballot_sync(FULL, kp);
        if (kp) buf[cpos + __popc(Kb & lmask)] = ee;
        cpos += __popc(Kb);
    }
    __syncwarp();
    *th = (t0 >= 63) ? 0xFFFFFFFFu : ((uint)(t0 + 209) << 22);
    return KN;
}

__global__ void __launch_bounds__(256, 2) k_knn()
{
    extern __shared__ char smem_raw[];
    float4* sc    = (float4*)smem_raw;                        // 65536
    float*  pn    = (float*)(smem_raw + 65536);               // 16384
    uint2*  bufs  = (uint2*)(smem_raw + 81920);               // 24576
    uint*   hists = (uint*)(smem_raw + 81920 + 24576);        // 4096
    uint2*  dump  = (uint2*)(smem_raw + 81920 + 24576 + 4096);// 2048

    int b = blockIdx.y;
    const float4* cp = (const float4*)(g_coords + b * NN * N_DIM);
    for (int i = threadIdx.x; i < NN; i += blockDim.x) {
        float4 v = cp[i];
        sc[i] = v;
        pn[i] = fmaf(v.x, v.x, fmaf(v.y, v.y, fmaf(v.z, v.z, v.w * v.w)));
    }
    __syncthreads();

    int w    = threadIdx.x >> 5;
    int lane = threadIdx.x & 31;
    int ql0  = 2 * w, ql1 = 2 * w + 1;
    int n0   = blockIdx.x * QPB + ql0;
    int n1   = n0 + 1;
    float4 q0 = sc[n0];
    float4 q1 = sc[n1];
    float qn0 = pn[n0], qn1 = pn[n1];
    float m0x = -2.f*q0.x, m0y = -2.f*q0.y, m0z = -2.f*q0.z, m0w = -2.f*q0.w;
    float m1x = -2.f*q1.x, m1y = -2.f*q1.y, m1z = -2.f*q1.z, m1w = -2.f*q1.w;
    uint2* buf0 = bufs + ql0 * NBUF;
    uint2* buf1 = bufs + ql1 * NBUF;
    uint*  h0   = hists + ql0 * 64;
    uint*  h1   = hists + ql1 * 64;
    uint2* dmp  = dump + w * 32 + lane;   // per-lane dump slot (branch-free store)
    uint lmask = (1u << lane) - 1u;

    uint th0 = FULL, th1 = FULL;
    int  c0 = 0, c1 = 0;

#pragma unroll 2
    for (int t = 0; t < 128; t++) {
        int j = lane + 32 * t;
        float4 p = sc[j];
        float pnj = pn[j];

        float d0 = pnj + qn0;
        d0 = fmaf(m0x, p.x, d0); d0 = fmaf(m0y, p.y, d0);
        d0 = fmaf(m0z, p.z, d0); d0 = fmaf(m0w, p.w, d0);
        d0 = fmaxf(d0, 0.f);
        uint k0 = (j == n0) ? FULL : __float_as_uint(d0);

        float d1 = pnj + qn1;
        d1 = fmaf(m1x, p.x, d1); d1 = fmaf(m1y, p.y, d1);
        d1 = fmaf(m1z, p.z, d1); d1 = fmaf(m1w, p.w, d1);
        d1 = fmaxf(d1, 0.f);
        uint k1 = (j == n1) ? FULL : __float_as_uint(d1);

        // branch-free accept: select destination, always store
        bool a0 = k0 < th0;
        uint A0 = __ballot_sync(FULL, a0);
        uint2* dst0 = a0 ? (buf0 + c0 + __popc(A0 & lmask)) : dmp;
        *dst0 = make_uint2(k0, (uint)j);
        c0 += __popc(A0);

        bool a1 = k1 < th1;
        uint A1 = __ballot_sync(FULL, a1);
        uint2* dst1 = a1 ? (buf1 + c1 + __popc(A1 & lmask)) : dmp;
        *dst1 = make_uint2(k1, (uint)j);
        c1 += __popc(A1);

        if ((c0 | c1) > 96) {           // warp-uniform, rarely taken
            if (c0 > 96) c0 = compact39(buf0, h0, c0, lane, lmask, &th0);
            if (c1 > 96) c1 = compact39(buf1, h1, c1, lane, lmask, &th1);
        }
    }
    if (c0 > KN) c0 = compact39(buf0, h0, c0, lane, lmask, &th0);
    if (c1 > KN) c1 = compact39(buf1, h1, c1, lane, lmask, &th1);

    int base0 = (b * NN + n0) * KN;
    int base1 = (b * NN + n1) * KN;
    for (int s = lane; s < KN; s += 32) {
        uint2 e0 = buf0[s];
        g_nbr_idx[base0 + s] = (int)e0.y;
        g_nbr_w[base0 + s]   = __expf(-10.0f * __uint_as_float(e0.x));
        uint2 e1 = buf1[s];
        g_nbr_idx[base1 + s] = (int)e1.y;
        g_nbr_w[base1 + s]   = __expf(-10.0f * __uint_as_float(e1.x));
    }
}

// ---------------------------------------------------------------------------
// K3: weighted gather -> max/mean -> concat -> @W_out + b_out  (unchanged)
// ---------------------------------------------------------------------------
__global__ void __launch_bounds__(256) k_agg(
    const float* __restrict__ x,
    const float* __restrict__ Wo, const float* __restrict__ bo,
    float* __restrict__ out)
{
    __shared__ float upd[32][192];
    int warp = threadIdx.x >> 5, lane = threadIdx.x & 31;
    int q0 = blockIdx.x * 32 + warp * 4;
    const float inv = 1.0f / 39.0f;

#pragma unroll
    for (int qq = 0; qq < 4; qq++) {
        int r = q0 + qq;
        const float* fb = g_features + (r >> 12) * NN * N_PROP;
        int bk = r * KN;
        float mx0 = -CUDART_INF_F, mx1 = -CUDART_INF_F, s0 = 0.f, s1 = 0.f;
#pragma unroll 8
        for (int k = 0; k < KN; k++) {
            int   jj = __ldg(&g_nbr_idx[bk + k]);
            float wt = __ldg(&g_nbr_w[bk + k]);
            float2 f = ((const float2*)(fb + jj * N_PROP))[lane];
            float v0 = wt * f.x, v1 = wt * f.y;
            mx0 = fmaxf(mx0, v0); mx1 = fmaxf(mx1, v1);
            s0 += v0; s1 += v1;
        }
        float2 xv = ((const float2*)(x + r * F_IN))[lane];
        int ql = warp * 4 + qq;
        upd[ql][2*lane]         = xv.x;
        upd[ql][2*lane + 1]     = xv.y;
        upd[ql][64 + 2*lane]    = mx0;
        upd[ql][64 + 2*lane+1]  = mx1;
        upd[ql][128 + 2*lane]   = s0 * inv;
        upd[ql][128 + 2*lane+1] = s1 * inv;
    }
    __syncwarp();

    float4 bv = ((const float4*)bo)[lane];
    float4 a0 = bv, a1 = bv, a2 = bv, a3 = bv;
    int ql0 = warp * 4;
#pragma unroll 4
    for (int c = 0; c < 192; c++) {
        float4 wv = ((const float4*)(Wo + c * N_FILT))[lane];
        float u0 = upd[ql0 + 0][c];
        float u1 = upd[ql0 + 1][c];
        float u2 = upd[ql0 + 2][c];
        float u3 = upd[ql0 + 3][c];
        a0.x = fmaf(u0, wv.x, a0.x); a0.y = fmaf(u0, wv.y, a0.y);
        a0.z = fmaf(u0, wv.z, a0.z); a0.w = fmaf(u0, wv.w, a0.w);
        a1.x = fmaf(u1, wv.x, a1.x); a1.y = fmaf(u1, wv.y, a1.y);
        a1.z = fmaf(u1, wv.z, a1.z); a1.w = fmaf(u1, wv.w, a1.w);
        a2.x = fmaf(u2, wv.x, a2.x); a2.y = fmaf(u2, wv.y, a2.y);
        a2.z = fmaf(u2, wv.z, a2.z); a2.w = fmaf(u2, wv.w, a2.w);
        a3.x = fmaf(u3, wv.x, a3.x); a3.y = fmaf(u3, wv.y, a3.y);
        a3.z = fmaf(u3, wv.z, a3.z); a3.w = fmaf(u3, wv.w, a3.w);
    }
    ((float4*)(out + (q0 + 0) * N_FILT))[lane] = a0;
    ((float4*)(out + (q0 + 1) * N_FILT))[lane] = a1;
    ((float4*)(out + (q0 + 2) * N_FILT))[lane] = a2;
    ((float4*)(out + (q0 + 3) * N_FILT))[lane] = a3;
}

// ---------------------------------------------------------------------------
extern "C" void kernel_launch(void* const* d_in, const int* in_sizes, int n_in,
                              void* d_out, int out_size)
{
    const float* x  = (const float*)d_in[0];
    const float* Wf = (const float*)d_in[1];
    const float* bf = (const float*)d_in[2];
    const float* Ws = (const float*)d_in[3];
    const float* bs = (const float*)d_in[4];
    const float* Wo = (const float*)d_in[5];
    const float* bo = (const float*)d_in[6];
    float* out = (float*)d_out;

    const int knn_smem = 65536 + 16384 + QPB * NBUF * 8 + QPB * 64 * 4 + 2048; // 112640
    cudaFuncSetAttribute(k_knn, cudaFuncAttributeMaxDynamicSharedMemorySize, knn_smem);

    k_feat<<<BB * NN / 32, 256>>>(x, Wf, bf, Ws, bs);

    dim3 g2(NN / QPB, BB);
    k_knn<<<g2, 256, knn_smem>>>();

    k_agg<<<BB * NN / 32, 256>>>(x, Wo, bo, out);
}

// round 11
// speedup vs baseline: 1.2289x; 1.1041x over previous
#include <cuda_runtime.h>
#include <math_constants.h>

// Problem constants
#define BB 4
#define NN 4096
#define F_IN 64
#define N_PROP 64
#define N_DIM 4
#define N_FILT 128
#define KN 39          // neighbors kept (top-40 minus self)
#define FULL 0xFFFFFFFFu
#define QPB 16         // queries per block (8 warps x 2)
#define NBUF 320       // per-query slots: live [0..256), staging [64..320)

// Scratch (allocation-free rule: __device__ globals)
__device__ float g_features[BB*NN*N_PROP];
__device__ float g_coords[BB*NN*N_DIM];
__device__ int   g_nbr_idx[BB*NN*KN];
__device__ float g_nbr_w[BB*NN*KN];

// ---------------------------------------------------------------------------
// K1: features = x@W_flr + b_flr ; coords = x@W_s + b_s  (unchanged, passing)
// ---------------------------------------------------------------------------
__global__ void __launch_bounds__(256) k_feat(
    const float* __restrict__ x,
    const float* __restrict__ Wf, const float* __restrict__ bf,
    const float* __restrict__ Ws, const float* __restrict__ bs)
{
    __shared__ float Wfs[64*64];
    __shared__ float Wss[64*4];
    __shared__ float xs[32][64];

    int t = threadIdx.x;
    int row0 = blockIdx.x * 32;

    for (int k = t; k < 64*64/4; k += 256) ((float4*)Wfs)[k] = ((const float4*)Wf)[k];
    if (t < 64) ((float4*)Wss)[t] = ((const float4*)Ws)[t];
    for (int k = t; k < 32*64/4; k += 256)
        ((float4*)xs)[k] = ((const float4*)(x + row0 * F_IN))[k];
    __syncthreads();

    int j = t & 63, rg = t >> 6;
    float b0 = bf[j];
    float a[8];
#pragma unroll
    for (int r = 0; r < 8; r++) a[r] = b0;
#pragma unroll
    for (int i = 0; i < 64; i++) {
        float wv = Wfs[i * 64 + j];
#pragma unroll
        for (int r = 0; r < 8; r++)
            a[r] = fmaf(xs[rg*8 + r][i], wv, a[r]);
    }
#pragma unroll
    for (int r = 0; r < 8; r++)
        g_features[(row0 + rg*8 + r) * N_PROP + j] = a[r];

    if (t < 128) {
        int r = t >> 2, c = t & 3;
        float a2 = bs[c];
#pragma unroll
        for (int i = 0; i < 64; i++)
            a2 = fmaf(xs[r][i], Wss[i * 4 + c], a2);
        g_coords[(row0 + r) * N_DIM + c] = a2;
    }
}

// ---------------------------------------------------------------------------
// K2: single-pass online-threshold exact top-39, 2 queries per warp.
// Inner loop: 4 branch-free candidate steps (select-address stores), then ONE
// compaction-trigger branch -> BSSY/BSYNC amortized 4x. Candidate norm
// recomputed (4 FMA shared by both queries) instead of a pn[] smem array.
// Capacity: between checks c grows <= 128; trigger at c>128 => c <= 256 = live.
// smem: float4 sc[4096] 64K | uint2 bufs[16][320] 40K | uint hists[16][64] 4K
//       | uint2 dump[8][32] 2K  => 110.6K, 2 blocks/SM
// ---------------------------------------------------------------------------
__device__ __forceinline__ int bin6(uint key) {
    int b = (int)(key >> 22) - 208;
    return max(0, min(63, b));
}

// Exact: keep the 39 lex-smallest (key,idx) of buf[0..M) into buf[0..39)
// (unordered), set *th to boundary-bin upper edge. Warp-collective, M<=256.
__device__ __forceinline__ int compact39(uint2* buf, uint* hist, int M,
                                         int lane, uint lmask, uint* th)
{
    hist[2*lane] = 0u; hist[2*lane + 1] = 0u;
    __syncwarp();
    uint2 e[8];
#pragma unroll
    for (int i = 0; i < 8; i++) {
        int s = lane + 32*i;
        if (s < M) { e[i] = buf[s]; atomicAdd(&hist[bin6(e[i].x)], 1u); }
    }
    __syncwarp();
    uint h0 = hist[2*lane], h1 = hist[2*lane + 1];
    int sum = (int)(h0 + h1), incl = sum;
#pragma unroll
    for (int o = 1; o < 32; o <<= 1) {
        int v = __shfl_up_sync(FULL, incl, o);
        if (lane >= o) incl += v;
    }
    int excl = incl - sum;
    uint ball = __ballot_sync(FULL, excl < KN && KN <= incl);
    int sel = __ffs(ball) - 1;
    int t0 = 0, nb = 0;
    if (lane == sel) {
        if (excl + (int)h0 >= KN) { t0 = 2*lane;     nb = excl; }
        else                      { t0 = 2*lane + 1; nb = excl + (int)h0; }
    }
    t0 = __shfl_sync(FULL, t0, sel);
    nb = __shfl_sync(FULL, nb, sel);
    int need = KN - nb;
    __syncwarp();

    // partition: bin<t0 -> buf[0..nb) (nb<=38<64), bin==t0 -> buf[64..64+bb)
    int ca = 0, bb = 0;
#pragma unroll
    for (int i = 0; i < 8; i++) {
        int s = lane + 32*i;
        bool act = s < M;
        int bn = act ? bin6(e[i].x) : 64;
        bool bel = bn < t0;
        bool bnd = bn == t0;
        uint A = __ballot_sync(FULL, bel);
        uint B = __ballot_sync(FULL, bnd);
        if (bel) buf[ca + __popc(A & lmask)] = e[i];
        if (bnd) buf[64 + bb + __popc(B & lmask)] = e[i];
        ca += __popc(A);
        bb += __popc(B);
    }
    __syncwarp();

    // exact rank within boundary set, fill remaining need slots
    int cpos = ca;                      // == nb
    for (int r0 = 0; r0 < bb; r0 += 32) {
        int s = r0 + lane;
        bool act = s < bb;
        uint2 ee = act ? buf[64 + s] : make_uint2(0u, 0u);
        int rank = 0;
        if (act) {
            for (int i = 0; i < bb; i++) {
                uint2 o = buf[64 + i];          // broadcast read
                rank += (o.x < ee.x) || (o.x == ee.x && o.y < ee.y);
            }
        }
        bool kp = act && rank < need;
        uint Kb = __ballot_sync(FULL, kp);
        if (kp) buf[cpos + __popc(Kb & lmask)] = ee;   // cpos..38 < 64
        cpos += __popc(Kb);
    }
    __syncwarp();
    *th = (t0 >= 63) ? 0xFFFFFFFFu : ((uint)(t0 + 209) << 22);
    return KN;
}

__global__ void __launch_bounds__(256, 2) k_knn()
{
    extern __shared__ char smem_raw[];
    float4* sc    = (float4*)smem_raw;                        // 65536
    uint2*  bufs  = (uint2*)(smem_raw + 65536);               // 40960
    uint*   hists = (uint*)(smem_raw + 65536 + 40960);        // 4096
    uint2*  dump  = (uint2*)(smem_raw + 65536 + 40960 + 4096);// 2048

    int b = blockIdx.y;
    const float4* cp = (const float4*)(g_coords + b * NN * N_DIM);
    for (int i = threadIdx.x; i < NN; i += blockDim.x) sc[i] = cp[i];
    __syncthreads();

    int w    = threadIdx.x >> 5;
    int lane = threadIdx.x & 31;
    int ql0  = 2 * w, ql1 = 2 * w + 1;
    int n0   = blockIdx.x * QPB + ql0;
    int n1   = n0 + 1;
    float4 q0 = sc[n0];
    float4 q1 = sc[n1];
    float qn0 = fmaf(q0.x, q0.x, fmaf(q0.y, q0.y, fmaf(q0.z, q0.z, q0.w * q0.w)));
    float qn1 = fmaf(q1.x, q1.x, fmaf(q1.y, q1.y, fmaf(q1.z, q1.z, q1.w * q1.w)));
    float m0x = -2.f*q0.x, m0y = -2.f*q0.y, m0z = -2.f*q0.z, m0w = -2.f*q0.w;
    float m1x = -2.f*q1.x, m1y = -2.f*q1.y, m1z = -2.f*q1.z, m1w = -2.f*q1.w;
    uint2* buf0 = bufs + ql0 * NBUF;
    uint2* buf1 = bufs + ql1 * NBUF;
    uint*  h0   = hists + ql0 * 64;
    uint*  h1   = hists + ql1 * 64;
    uint2* dmp  = dump + w * 32 + lane;
    uint lmask = (1u << lane) - 1u;

    uint th0 = FULL, th1 = FULL;
    int  c0 = 0, c1 = 0;

    for (int tt = 0; tt < 32; tt++) {
#pragma unroll
        for (int u = 0; u < 4; u++) {        // branch-free candidate steps
            int j = lane + 32 * (4*tt + u);
            float4 p = sc[j];
            float pnj = fmaf(p.x, p.x, fmaf(p.y, p.y, fmaf(p.z, p.z, p.w * p.w)));

            float d0 = pnj + qn0;
            d0 = fmaf(m0x, p.x, d0); d0 = fmaf(m0y, p.y, d0);
            d0 = fmaf(m0z, p.z, d0); d0 = fmaf(m0w, p.w, d0);
            d0 = fmaxf(d0, 0.f);
            uint k0 = (j == n0) ? FULL : __float_as_uint(d0);

            float d1 = pnj + qn1;
            d1 = fmaf(m1x, p.x, d1); d1 = fmaf(m1y, p.y, d1);
            d1 = fmaf(m1z, p.z, d1); d1 = fmaf(m1w, p.w, d1);
            d1 = fmaxf(d1, 0.f);
            uint k1 = (j == n1) ? FULL : __float_as_uint(d1);

            bool a0 = k0 < th0;
            uint A0 = __ballot_sync(FULL, a0);
            uint2* dst0 = a0 ? (buf0 + c0 + __popc(A0 & lmask)) : dmp;
            *dst0 = make_uint2(k0, (uint)j);
            c0 += __popc(A0);

            bool a1 = k1 < th1;
            uint A1 = __ballot_sync(FULL, a1);
            uint2* dst1 = a1 ? (buf1 + c1 + __popc(A1 & lmask)) : dmp;
            *dst1 = make_uint2(k1, (uint)j);
            c1 += __popc(A1);
        }
        if ((c0 | c1) > 128) {               // one branch per 4 iterations
            if (c0 > 128) c0 = compact39(buf0, h0, c0, lane, lmask, &th0);
            if (c1 > 128) c1 = compact39(buf1, h1, c1, lane, lmask, &th1);
        }
    }
    if (c0 > KN) c0 = compact39(buf0, h0, c0, lane, lmask, &th0);
    if (c1 > KN) c1 = compact39(buf1, h1, c1, lane, lmask, &th1);

    int base0 = (b * NN + n0) * KN;
    int base1 = (b * NN + n1) * KN;
    for (int s = lane; s < KN; s += 32) {
        uint2 e0 = buf0[s];
        g_nbr_idx[base0 + s] = (int)e0.y;
        g_nbr_w[base0 + s]   = __expf(-10.0f * __uint_as_float(e0.x));
        uint2 e1 = buf1[s];
        g_nbr_idx[base1 + s] = (int)e1.y;
        g_nbr_w[base1 + s]   = __expf(-10.0f * __uint_as_float(e1.x));
    }
}

// ---------------------------------------------------------------------------
// K3: weighted gather -> max/mean -> concat -> @W_out + b_out  (unchanged)
// ---------------------------------------------------------------------------
__global__ void __launch_bounds__(256) k_agg(
    const float* __restrict__ x,
    const float* __restrict__ Wo, const float* __restrict__ bo,
    float* __restrict__ out)
{
    __shared__ float upd[32][192];
    int warp = threadIdx.x >> 5, lane = threadIdx.x & 31;
    int q0 = blockIdx.x * 32 + warp * 4;
    const float inv = 1.0f / 39.0f;

#pragma unroll
    for (int qq = 0; qq < 4; qq++) {
        int r = q0 + qq;
        const float* fb = g_features + (r >> 12) * NN * N_PROP;
        int bk = r * KN;
        float mx0 = -CUDART_INF_F, mx1 = -CUDART_INF_F, s0 = 0.f, s1 = 0.f;
#pragma unroll 8
        for (int k = 0; k < KN; k++) {
            int   jj = __ldg(&g_nbr_idx[bk + k]);
            float wt = __ldg(&g_nbr_w[bk + k]);
            float2 f = ((const float2*)(fb + jj * N_PROP))[lane];
            float v0 = wt * f.x, v1 = wt * f.y;
            mx0 = fmaxf(mx0, v0); mx1 = fmaxf(mx1, v1);
            s0 += v0; s1 += v1;
        }
        float2 xv = ((const float2*)(x + r * F_IN))[lane];
        int ql = warp * 4 + qq;
        upd[ql][2*lane]         = xv.x;
        upd[ql][2*lane + 1]     = xv.y;
        upd[ql][64 + 2*lane]    = mx0;
        upd[ql][64 + 2*lane+1]  = mx1;
        upd[ql][128 + 2*lane]   = s0 * inv;
        upd[ql][128 + 2*lane+1] = s1 * inv;
    }
    __syncwarp();

    float4 bv = ((const float4*)bo)[lane];
    float4 a0 = bv, a1 = bv, a2 = bv, a3 = bv;
    int ql0 = warp * 4;
#pragma unroll 4
    for (int c = 0; c < 192; c++) {
        float4 wv = ((const float4*)(Wo + c * N_FILT))[lane];
        float u0 = upd[ql0 + 0][c];
        float u1 = upd[ql0 + 1][c];
        float u2 = upd[ql0 + 2][c];
        float u3 = upd[ql0 + 3][c];
        a0.x = fmaf(u0, wv.x, a0.x); a0.y = fmaf(u0, wv.y, a0.y);
        a0.z = fmaf(u0, wv.z, a0.z); a0.w = fmaf(u0, wv.w, a0.w);
        a1.x = fmaf(u1, wv.x, a1.x); a1.y = fmaf(u1, wv.y, a1.y);
        a1.z = fmaf(u1, wv.z, a1.z); a1.w = fmaf(u1, wv.w, a1.w);
        a2.x = fmaf(u2, wv.x, a2.x); a2.y = fmaf(u2, wv.y, a2.y);
        a2.z = fmaf(u2, wv.z, a2.z); a2.w = fmaf(u2, wv.w, a2.w);
        a3.x = fmaf(u3, wv.x, a3.x); a3.y = fmaf(u3, wv.y, a3.y);
        a3.z = fmaf(u3, wv.z, a3.z); a3.w = fmaf(u3, wv.w, a3.w);
    }
    ((float4*)(out + (q0 + 0) * N_FILT))[lane] = a0;
    ((float4*)(out + (q0 + 1) * N_FILT))[lane] = a1;
    ((float4*)(out + (q0 + 2) * N_FILT))[lane] = a2;
    ((float4*)(out + (q0 + 3) * N_FILT))[lane] = a3;
}

// ---------------------------------------------------------------------------
extern "C" void kernel_launch(void* const* d_in, const int* in_sizes, int n_in,
                              void* d_out, int out_size)
{
    const float* x  = (const float*)d_in[0];
    const float* Wf = (const float*)d_in[1];
    const float* bf = (const float*)d_in[2];
    const float* Ws = (const float*)d_in[3];
    const float* bs = (const float*)d_in[4];
    const float* Wo = (const float*)d_in[5];
    const float* bo = (const float*)d_in[6];
    float* out = (float*)d_out;

    const int knn_smem = 65536 + QPB * NBUF * 8 + QPB * 64 * 4 + 2048; // 112640
    cudaFuncSetAttribute(k_knn, cudaFuncAttributeMaxDynamicSharedMemorySize, knn_smem);

    k_feat<<<BB * NN / 32, 256>>>(x, Wf, bf, Ws, bs);

    dim3 g2(NN / QPB, BB);
    k_knn<<<g2, 256, knn_smem>>>();

    k_agg<<<BB * NN / 32, 256>>>(x, Wo, bo, out);
}